// round 5
// baseline (speedup 1.0000x reference)
#include <cuda_runtime.h>
#include <cuda_bf16.h>
#include <math.h>

#define NN 50000
#define EE 800000
#define ETOT (EE + NN)
#define NB 49              // ceil(NN/1024)
#define EPS 1e-5f

// ---------------- device scratch ----------------
__device__ float d_bufA[NN * 64];
__device__ float d_bufB[NN * 64];
__device__ float d_bufC[NN * 64];
__device__ float d_es[NN * 2];
__device__ float d_ed[NN * 2];
__device__ int   d_cnt[NN];
__device__ int   d_scan[NN];
__device__ int   d_rowptr[NN + 1];
__device__ int   d_cursor[NN];
__device__ int   d_col[ETOT];
__device__ int   d_btot[NB];
__device__ int   d_boff[NB];
__device__ float d_bnacc[320];   // L1:[sum64|sq64] L2:[sum64|sq64] L3:[sum32|sq32]

// ---------------- f32x2 helpers ----------------
__device__ __forceinline__ void fma2(unsigned long long& d, unsigned long long a,
                                     unsigned long long b) {
    asm("fma.rn.f32x2 %0, %1, %2, %0;" : "+l"(d) : "l"(a), "l"(b));
}
__device__ __forceinline__ unsigned long long pk2(float x) {
    unsigned long long r;
    asm("mov.b64 %0, {%1, %1};" : "=l"(r) : "f"(x));
    return r;
}
union U64F2 { unsigned long long u; float2 f; };

// ---------------- init ----------------
__global__ void zero_k() {
    int i = blockIdx.x * 256 + threadIdx.x;
    if (i < NN) d_cnt[i] = 0;
    if (i < 320) d_bnacc[i] = 0.f;
}

__global__ void count_k(const int* __restrict__ dst) {
    int i = blockIdx.x * 256 + threadIdx.x;
    if (i >= ETOT) return;
    int d = (i < EE) ? __ldg(&dst[i]) : (i - EE);
    atomicAdd(&d_cnt[d], 1);
}

__global__ void scan1_k() {
    __shared__ int wsum[32];
    int g = blockIdx.x * 1024 + threadIdx.x;
    int lane = threadIdx.x & 31, wid = threadIdx.x >> 5;
    int v = (g < NN) ? d_cnt[g] : 0;
    int x = v;
#pragma unroll
    for (int o = 1; o < 32; o <<= 1) {
        int t = __shfl_up_sync(0xffffffffu, x, o);
        if (lane >= o) x += t;
    }
    if (lane == 31) wsum[wid] = x;
    __syncthreads();
    if (wid == 0) {
        int w = wsum[lane];
#pragma unroll
        for (int o = 1; o < 32; o <<= 1) {
            int t = __shfl_up_sync(0xffffffffu, w, o);
            if (lane >= o) w += t;
        }
        wsum[lane] = w;
    }
    __syncthreads();
    int incl = x + (wid ? wsum[wid - 1] : 0);
    if (g < NN) d_scan[g] = incl;
    if (threadIdx.x == 1023) d_btot[blockIdx.x] = incl;
}

__global__ void scan2_k() {   // 64 threads, NB=49
    int t = threadIdx.x;
    int lane = t & 31, w = t >> 5;
    int v = (t < NB) ? d_btot[t] : 0;
    int x = v;
#pragma unroll
    for (int o = 1; o < 32; o <<= 1) {
        int s = __shfl_up_sync(0xffffffffu, x, o);
        if (lane >= o) x += s;
    }
    __shared__ int s0;
    if (w == 0 && lane == 31) s0 = x;
    __syncthreads();
    int incl = x + (w ? s0 : 0);
    if (t < NB) d_boff[t] = incl - v;
}

__global__ void scan3_k() {
    int i = blockIdx.x * 256 + threadIdx.x;
    if (i >= NN) return;
    int incl = d_scan[i] + d_boff[i >> 10];
    int excl = incl - d_cnt[i];
    d_rowptr[i] = excl;
    d_cursor[i] = excl;
    if (i == NN - 1) d_rowptr[NN] = incl;
}

__global__ void scatter_k(const int* __restrict__ src, const int* __restrict__ dst) {
    int i = blockIdx.x * 256 + threadIdx.x;
    if (i >= ETOT) return;
    int s, d;
    if (i < EE) { s = __ldg(&src[i]); d = __ldg(&dst[i]); }
    else        { s = i - EE; d = s; }
    int pos = atomicAdd(&d_cursor[d], 1);
    d_col[pos] = s;
}

// ---- fused GEMM (f32x2, column-pair packed) + BN-from-acc input + es/ed epilogue --
// Same data flow as the R4-proven scalar kernel; only the FMA register packing
// changed: u64 accumulator = adjacent column pair, W read as natural ulonglong2.
template<int K, int NC, bool BN, int H>
__global__ void __launch_bounds__(256) gemm_k(
    const float* __restrict__ X, const float* __restrict__ W,
    const float* __restrict__ asv, const float* __restrict__ adv,
    const float* __restrict__ accIn, const float* __restrict__ g,
    const float* __restrict__ be, float* __restrict__ Hout)
{
    constexpr int KT  = 32;            // K-chunk
    constexpr int CT  = NC / 8;        // col threads: 8 (NC=64) or 4 (NC=32)
    constexpr int RT  = 256 / CT;      // 32 or 64
    constexpr int RPB = RT * 4;        // 128 or 256 rows per block
    __shared__ float sX[RPB * KT];
    __shared__ float sW[KT * NC];
    __shared__ float sS[BN ? 64 : 1];
    __shared__ float sT[BN ? 64 : 1];

    if (BN) {
        if (threadIdx.x < K) {
            float mu  = accIn[threadIdx.x] * (1.f / NN);
            float var = fmaf(-mu, mu, accIn[K + threadIdx.x] * (1.f / NN));
            float sc  = rsqrtf(var + EPS) * g[threadIdx.x];
            sS[threadIdx.x] = sc;
            sT[threadIdx.x] = be[threadIdx.x] - mu * sc;
        }
    }
    const int ct = threadIdx.x % CT;
    const int rt = threadIdx.x / CT;
    const int r0 = blockIdx.x * RPB;
    const int row0 = rt * 4;

    unsigned long long acc[4][4];
#pragma unroll
    for (int i = 0; i < 4; i++)
#pragma unroll
        for (int c = 0; c < 4; c++) acc[i][c] = 0ull;

    for (int kt = 0; kt < K; kt += KT) {
        __syncthreads();
        // stage W chunk [KT x NC]
#pragma unroll
        for (int i = threadIdx.x; i < KT * NC / 4; i += 256) {
            reinterpret_cast<float4*>(sW)[i] =
                __ldg(reinterpret_cast<const float4*>(W) + (size_t)kt * (NC / 4) + i);
        }
        // stage X chunk [RPB x KT] with optional BN+ReLU
#pragma unroll
        for (int i = threadIdx.x; i < RPB * (KT / 4); i += 256) {
            int r = i / (KT / 4), c4 = i % (KT / 4);
            int gr = r0 + r;
            float4 v = make_float4(0.f, 0.f, 0.f, 0.f);
            if (gr < NN)
                v = *reinterpret_cast<const float4*>(X + (size_t)gr * K + kt + c4 * 4);
            if (BN) {
                int kk = kt + c4 * 4;
                v.x = fmaxf(fmaf(v.x, sS[kk + 0], sT[kk + 0]), 0.f);
                v.y = fmaxf(fmaf(v.y, sS[kk + 1], sT[kk + 1]), 0.f);
                v.z = fmaxf(fmaf(v.z, sS[kk + 2], sT[kk + 2]), 0.f);
                v.w = fmaxf(fmaf(v.w, sS[kk + 3], sT[kk + 3]), 0.f);
            }
            reinterpret_cast<float4*>(sX)[i] = v;
        }
        __syncthreads();
#pragma unroll
        for (int k = 0; k < KT; k += 4) {
            float4 x0 = *reinterpret_cast<const float4*>(sX + (row0 + 0) * KT + k);
            float4 x1 = *reinterpret_cast<const float4*>(sX + (row0 + 1) * KT + k);
            float4 x2 = *reinterpret_cast<const float4*>(sX + (row0 + 2) * KT + k);
            float4 x3 = *reinterpret_cast<const float4*>(sX + (row0 + 3) * KT + k);
#pragma unroll
            for (int kk = 0; kk < 4; kk++) {
                ulonglong2 wa = *reinterpret_cast<const ulonglong2*>(
                    sW + (k + kk) * NC + ct * 8);
                ulonglong2 wb = *reinterpret_cast<const ulonglong2*>(
                    sW + (k + kk) * NC + ct * 8 + 4);
                unsigned long long xp0 = pk2((&x0.x)[kk]);
                unsigned long long xp1 = pk2((&x1.x)[kk]);
                unsigned long long xp2 = pk2((&x2.x)[kk]);
                unsigned long long xp3 = pk2((&x3.x)[kk]);
                fma2(acc[0][0], xp0, wa.x); fma2(acc[0][1], xp0, wa.y);
                fma2(acc[0][2], xp0, wb.x); fma2(acc[0][3], xp0, wb.y);
                fma2(acc[1][0], xp1, wa.x); fma2(acc[1][1], xp1, wa.y);
                fma2(acc[1][2], xp1, wb.x); fma2(acc[1][3], xp1, wb.y);
                fma2(acc[2][0], xp2, wa.x); fma2(acc[2][1], xp2, wa.y);
                fma2(acc[2][2], xp2, wb.x); fma2(acc[2][3], xp2, wb.y);
                fma2(acc[3][0], xp3, wa.x); fma2(acc[3][1], xp3, wa.y);
                fma2(acc[3][2], xp3, wb.x); fma2(acc[3][3], xp3, wb.y);
            }
        }
    }

    // epilogue: unpack, store H, fused es/ed (shfl over the ct-lanes of each head)
    float as_[8], ad_[8];
#pragma unroll
    for (int c = 0; c < 8; c++) {
        as_[c] = __ldg(asv + ct * 8 + c);
        ad_[c] = __ldg(adv + ct * 8 + c);
    }
#pragma unroll
    for (int i = 0; i < 4; i++) {
        int gr = r0 + row0 + i;
        float v[8];
#pragma unroll
        for (int c = 0; c < 4; c++) {
            U64F2 t; t.u = acc[i][c];
            v[2 * c]     = t.f.x;
            v[2 * c + 1] = t.f.y;
        }
        float ps = 0.f, pd = 0.f;
#pragma unroll
        for (int c = 0; c < 8; c++) {
            ps = fmaf(v[c], as_[c], ps);
            pd = fmaf(v[c], ad_[c], pd);
        }
        // reduce over the 4 ct-lanes of this head (ct bits are lane bits 0..1(+2))
        ps += __shfl_xor_sync(0xffffffffu, ps, 1);
        pd += __shfl_xor_sync(0xffffffffu, pd, 1);
        ps += __shfl_xor_sync(0xffffffffu, ps, 2);
        pd += __shfl_xor_sync(0xffffffffu, pd, 2);
        if (gr < NN) {
            *reinterpret_cast<float4*>(Hout + (size_t)gr * NC + ct * 8) =
                make_float4(v[0], v[1], v[2], v[3]);
            *reinterpret_cast<float4*>(Hout + (size_t)gr * NC + ct * 8 + 4) =
                make_float4(v[4], v[5], v[6], v[7]);
            if (NC == 64) {
                if (ct == 0) { d_es[gr * 2]     = ps; d_ed[gr * 2]     = pd; }
                if (ct == 4) { d_es[gr * 2 + 1] = ps; d_ed[gr * 2 + 1] = pd; }
            } else {
                if (ct == 0) { d_es[gr] = ps; d_ed[gr] = pd; }
            }
        }
    }
}

// -------- GAT aggregation (warp/node) + fused BN stats (smem tree + atomics) ------
__device__ __forceinline__ float lrelu(float x) { return fmaxf(x, 0.2f * x); }

template<int H>
__global__ void __launch_bounds__(512) agg_k(const float* __restrict__ Hm,
                                             const float* __restrict__ bias,
                                             float* __restrict__ out,
                                             float* __restrict__ accOut) {
    __shared__ float red[16][128];
    int w = threadIdx.x >> 5;
    int l = threadIdx.x & 31;
    int node = blockIdx.x * 16 + w;

    if (H == 2) {
        float o0 = 0.f, o1 = 0.f;
        if (node < NN) {
            int beg = __ldg(&d_rowptr[node]);
            int end = __ldg(&d_rowptr[node + 1]);
            const float2 edv = reinterpret_cast<const float2*>(d_ed)[node];
            const float2* es2 = reinterpret_cast<const float2*>(d_es);
            float dn0 = 0.f, dn1 = 0.f, a0 = 0.f, a1 = 0.f;
#pragma unroll 4
            for (int j = beg; j < end; j++) {
                int s = __ldg(&d_col[j]);
                float2 e = __ldg(&es2[s]);
                float p0 = __expf(lrelu(e.x + edv.x));
                float p1 = __expf(lrelu(e.y + edv.y));
                const float* hr = Hm + (size_t)s * 64;
                dn0 += p0; dn1 += p1;
                a0 = fmaf(p0, __ldg(hr + l), a0);
                a1 = fmaf(p1, __ldg(hr + 32 + l), a1);
            }
            o0 = a0 / (dn0 + 1e-16f) + __ldg(bias + l);
            o1 = a1 / (dn1 + 1e-16f) + __ldg(bias + 32 + l);
            out[(size_t)node * 64 + l]      = o0;
            out[(size_t)node * 64 + 32 + l] = o1;
        }
        red[w][l]      = o0;
        red[w][32 + l] = o1;
        red[w][64 + l] = o0 * o0;
        red[w][96 + l] = o1 * o1;
        __syncthreads();
        if (threadIdx.x < 128) {
            float s = 0.f;
#pragma unroll
            for (int i = 0; i < 16; i++) s += red[i][threadIdx.x];
            atomicAdd(&accOut[threadIdx.x], s);
        }
    } else {
        float o = 0.f;
        if (node < NN) {
            int beg = __ldg(&d_rowptr[node]);
            int end = __ldg(&d_rowptr[node + 1]);
            float edv = d_ed[node];
            float dn = 0.f, a = 0.f;
#pragma unroll 4
            for (int j = beg; j < end; j++) {
                int s = __ldg(&d_col[j]);
                float p = __expf(lrelu(__ldg(&d_es[s]) + edv));
                dn += p;
                a = fmaf(p, __ldg(Hm + (size_t)s * 32 + l), a);
            }
            o = a / (dn + 1e-16f) + __ldg(bias + l);
            out[(size_t)node * 32 + l] = o;
        }
        red[w][l]      = o;
        red[w][32 + l] = o * o;
        __syncthreads();
        if (threadIdx.x < 64) {
            float s = 0.f;
#pragma unroll
            for (int i = 0; i < 16; i++) s += red[i][threadIdx.x];
            atomicAdd(&accOut[threadIdx.x], s);
        }
    }
}

// final BN apply + ReLU -> out (stats direct from acc)
__global__ void bnapply3_k(const float* __restrict__ X, const float* __restrict__ acc,
                           const float* __restrict__ g, const float* __restrict__ be,
                           float* __restrict__ Y) {
    int idx = blockIdx.x * 256 + threadIdx.x;
    if (idx >= NN * 32) return;
    int c = idx & 31;
    float mu  = acc[c] * (1.f / NN);
    float var = fmaf(-mu, mu, acc[32 + c] * (1.f / NN));
    float y = (X[idx] - mu) * rsqrtf(var + EPS) * g[c] + be[c];
    Y[idx] = fmaxf(y, 0.f);
}

// ---------------- launch ----------------
static inline int cdiv(int a, int b) { return (a + b - 1) / b; }

extern "C" void kernel_launch(void* const* d_in, const int* in_sizes, int n_in,
                              void* d_out, int out_size) {
    const float* x   = (const float*)d_in[0];
    const float* W1  = (const float*)d_in[1];
    const float* as1 = (const float*)d_in[2];
    const float* ad1 = (const float*)d_in[3];
    const float* b1  = (const float*)d_in[4];
    const float* g1  = (const float*)d_in[5];
    const float* be1 = (const float*)d_in[6];
    const float* W2  = (const float*)d_in[7];
    const float* as2 = (const float*)d_in[8];
    const float* ad2 = (const float*)d_in[9];
    const float* b2  = (const float*)d_in[10];
    const float* g2  = (const float*)d_in[11];
    const float* be2 = (const float*)d_in[12];
    const float* W3  = (const float*)d_in[13];
    const float* as3 = (const float*)d_in[14];
    const float* ad3 = (const float*)d_in[15];
    const float* b3  = (const float*)d_in[16];
    const float* g3  = (const float*)d_in[17];
    const float* be3 = (const float*)d_in[18];
    const int*   ei  = (const int*)d_in[19];
    const int* esrc = ei;
    const int* edst = ei + EE;

    float* bufA; cudaGetSymbolAddress((void**)&bufA, d_bufA);
    float* bufB; cudaGetSymbolAddress((void**)&bufB, d_bufB);
    float* bufC; cudaGetSymbolAddress((void**)&bufC, d_bufC);
    float* bnac; cudaGetSymbolAddress((void**)&bnac, d_bnacc);
    float* outp = (float*)d_out;

    const int aggBlocks = cdiv(NN, 16);   // 3125

    // CSR build; gemm1 interleaved (independent of CSR)
    zero_k<<<cdiv(NN, 256), 256>>>();
    count_k<<<cdiv(ETOT, 256), 256>>>(edst);
    scan1_k<<<NB, 1024>>>();
    gemm_k<128, 64, false, 2><<<cdiv(NN, 128), 256>>>(
        x, W1, as1, ad1, nullptr, nullptr, nullptr, bufB);
    scan2_k<<<1, 64>>>();
    scan3_k<<<cdiv(NN, 256), 256>>>();
    scatter_k<<<cdiv(ETOT, 256), 256>>>(esrc, edst);

    // layer 1 aggregation (+BN1 stats)
    agg_k<2><<<aggBlocks, 512>>>(bufB, b1, bufC, bnac + 0);

    // layer 2 (BN1+ReLU fused into X staging)
    gemm_k<64, 64, true, 2><<<cdiv(NN, 128), 256>>>(
        bufC, W2, as2, ad2, bnac + 0, g1, be1, bufB);
    agg_k<2><<<aggBlocks, 512>>>(bufB, b2, bufC, bnac + 128);

    // layer 3 (BN2+ReLU fused into X staging)
    gemm_k<64, 32, true, 1><<<cdiv(NN, 256), 256>>>(
        bufC, W3, as3, ad3, bnac + 128, g2, be2, bufA);
    agg_k<1><<<aggBlocks, 512>>>(bufA, b3, bufC, bnac + 256);
    bnapply3_k<<<cdiv(NN * 32, 256), 256>>>(bufC, bnac + 256, g3, be3, outp);
}